// round 9
// baseline (speedup 1.0000x reference)
#include <cuda_runtime.h>
#include <cuda_fp16.h>
#include <cstdint>

#define BB 64
#define HH 256
#define WW 256
#define TH 32                      // output rows per tile
#define NT 256
#define ARMAX (TH + 10)            // 42 rows (R=5 halo)
#define LUTN 2048                  // 2^11 entries for R=5
// smem: LUT 8192B | Bs 43008B | Os 16384B
#define OFF_BS  (LUTN * 4)
#define OFF_OS  (OFF_BS + ARMAX * WW * 4)
#define SMEM_BYTES (OFF_OS + TH * (WW / 2) * 4)   // 67584

typedef unsigned long long ull;

__device__ __align__(16) uint32_t g_bits[3][BB][HH][8];      // 1 bit/px masks
__device__ __align__(16) uint32_t g_maph[BB][HH * WW / 2];   // fp16x2 target map (cross-block)
__device__ float g_max[3 * BB];        // zero-init; atomicMax idempotent across replays
__device__ unsigned g_done[3 * BB];    // monotonic arrival counters (epoch barrier)

__device__ __forceinline__ int map_ch(int m) { return (m == 0) ? 2 : (m == 1) ? 1 : 3; }

// ---- packed f32x2 helpers (sm_103a) ----
__device__ __forceinline__ ull f2pack(uint32_t lo, uint32_t hi) {
    ull r; asm("mov.b64 %0, {%1, %2};" : "=l"(r) : "r"(lo), "r"(hi)); return r;
}
__device__ __forceinline__ void f2unpack(ull v, float& lo, float& hi) {
    asm("mov.b64 {%0, %1}, %2;" : "=f"(lo), "=f"(hi) : "l"(v));
}
__device__ __forceinline__ ull f2add(ull a, ull b) {
    ull r; asm("add.rn.f32x2 %0, %1, %2;" : "=l"(r) : "l"(a), "l"(b)); return r;
}
__device__ __forceinline__ ull f2mul(ull a, ull b) {
    ull r; asm("mul.rn.f32x2 %0, %1, %2;" : "=l"(r) : "l"(a), "l"(b)); return r;
}
__device__ __forceinline__ ull f2fma(ull a, ull b, ull c) {
    ull r; asm("fma.rn.f32x2 %0, %1, %2, %3;" : "=l"(r) : "l"(a), "l"(b), "l"(c)); return r;
}

// ============ Kernel 1: threshold channels into bit array + ch0 copy ============
__global__ void __launch_bounds__(NT) bitK(const float* __restrict__ x,
                                           float* __restrict__ out) {
    const int b = blockIdx.y;
    const int z = blockIdx.z;
    const size_t plane = (size_t)HH * WW;

    if (z == 3) {                       // ch0 passthrough: 8192 floats per block
        const size_t off = (size_t)blockIdx.x * 8192;
        const float4* s = (const float4*)(x + (size_t)b * 4 * plane + off);
        float4* d = (float4*)(out + (size_t)b * 5 * plane + off);
#pragma unroll
        for (int k = 0; k < 8; k++)
            d[threadIdx.x + 256 * k] = s[threadIdx.x + 256 * k];
        return;
    }

    const int m = z;
    const float* src = x + ((size_t)b * 4 + map_ch(m)) * plane;
    const int warp = threadIdx.x >> 5;
    const int lane = threadIdx.x & 31;
    const int r0 = blockIdx.x * 32 + warp * 4;

#pragma unroll
    for (int rr = 0; rr < 4; rr++) {
        const int r = r0 + rr;
        const float* rp = src + (size_t)r * WW;
        float v[8];
#pragma unroll
        for (int k = 0; k < 8; k++) v[k] = rp[32 * k + lane];
        uint32_t mine = 0;
#pragma unroll
        for (int k = 0; k < 8; k++) {
            uint32_t w = __ballot_sync(0xFFFFFFFFu, v[k] > 0.f);
            if (lane == k) mine = w;
        }
        if (lane < 8) g_bits[m][b][r][lane] = mine;
    }
}

// ============ LUT build ============
template <int R>
__device__ __forceinline__ void buildLUT(const float* wg, float* LUT) {
    if constexpr (R == 5) {
        const int t = threadIdx.x;
        float base = 0.f;
#pragma unroll
        for (int b = 0; b < 8; b++) {
            int pos = b + 3;
            int ai = (pos < 5) ? (5 - pos) : (pos - 5);
            if ((t >> b) & 1) base += wg[ai];
        }
        float comb[8];
        comb[0] = 0.f;           comb[1] = wg[5];
        comb[2] = wg[4];         comb[3] = wg[5] + wg[4];
        comb[4] = wg[3];         comb[5] = wg[3] + wg[5];
        comb[6] = wg[3] + wg[4]; comb[7] = wg[3] + wg[4] + wg[5];
#pragma unroll
        for (int j = 0; j < 8; j++) LUT[t * 8 + j] = base + comb[j];
    } else {
        if (threadIdx.x < 32) {
            const int i = threadIdx.x;
            float s = 0.f;
#pragma unroll
            for (int b = 0; b < 5; b++) {
                int ai = (b < 2) ? (2 - b) : (b - 2);
                if ((i >> b) & 1) s += wg[ai];
            }
            LUT[i] = s;
        }
    }
}

// H-conv: thread owns col pair x 16 rows; stores fp16x2 into smem Os (+ global for m=0).
template <int R, bool WRITEG>
__device__ __forceinline__ float hconv2(const float* __restrict__ Bs, const ull* w2,
                                        uint32_t* __restrict__ Os,
                                        uint32_t* __restrict__ gdst, int row0,
                                        int jc, int tg) {
    const int t0 = tg * 16;
    ull win[2 * R + 1];
#pragma unroll
    for (int k = 0; k < 2 * R + 1; k++)
        win[k] = *(const ull*)(Bs + (t0 + k) * WW + jc);
    float mx = 0.f;
#pragma unroll
    for (int t = 0; t < 16; t++) {
        ull acc = f2mul(w2[0], win[R]);
#pragma unroll
        for (int d = 1; d <= R; d++)
            acc = f2fma(w2[d], f2add(win[R - d], win[R + d]), acc);
        float lo, hi; f2unpack(acc, lo, hi);
        uint32_t h2;
        asm("cvt.rn.f16x2.f32 %0, %1, %2;" : "=r"(h2) : "f"(hi), "f"(lo));
        Os[(t0 + t) * (WW / 2) + (jc >> 1)] = h2;
        if (WRITEG)
            gdst[(size_t)(row0 + t0 + t) * (WW / 2) + (jc >> 1)] = h2;
        mx = fmaxf(mx, fmaxf(lo, hi));
#pragma unroll
        for (int k = 0; k < 2 * R; k++) win[k] = win[k + 1];
        if (t < 15) win[2 * R] = *(const ull*)(Bs + (t0 + t + 1 + 2 * R) * WW + jc);
    }
    return mx;
}

__device__ __forceinline__ void groupWait(unsigned* cnt, unsigned target) {
    while (*(volatile unsigned*)cnt < target) __nanosleep(64);
}

template <int R, int M>
__device__ __forceinline__ void runMapFin(int b, float i2s, int row0,
                                          float* LUT, float* Bs, uint32_t* Os,
                                          float* red, float* __restrict__ out) {
    constexpr int W = 2 * R + 1;
    constexpr int AR = TH + 2 * R;

    float wg[R + 1];
#pragma unroll
    for (int d = 0; d <= R; d++) wg[d] = __expf(-(float)(d * d) * i2s);

    buildLUT<R>(wg, LUT);
    __syncthreads();

    // W-conv from L2-resident bit array.
    const int warp = threadIdx.x >> 5;
    const int lane = threadIdx.x & 31;
    const unsigned off = (lane - R) & 31u;
    const bool sel = (lane >= R);
    for (int r = warp; r < AR; r += NT / 32) {
        const int gr = row0 - R + r;
        uint32_t rb[10];
        rb[0] = 0u; rb[9] = 0u;
        if ((unsigned)gr < HH) {
            uint4 a = *(const uint4*)&g_bits[M][b][gr][0];
            uint4 c = *(const uint4*)&g_bits[M][b][gr][4];
            rb[1] = a.x; rb[2] = a.y; rb[3] = a.z; rb[4] = a.w;
            rb[5] = c.x; rb[6] = c.y; rb[7] = c.z; rb[8] = c.w;
        } else {
#pragma unroll
            for (int k = 1; k < 9; k++) rb[k] = 0u;
        }
        uint32_t f[9];
#pragma unroll
        for (int k = 0; k < 9; k++) f[k] = __funnelshift_r(rb[k], rb[k + 1], off);
#pragma unroll
        for (int k = 0; k < 8; k++) {
            uint32_t idx = (sel ? f[k + 1] : f[k]) & ((1u << W) - 1u);
            Bs[r * WW + 32 * k + lane] = LUT[idx];
        }
    }
    __syncthreads();

    ull w2[R + 1];
#pragma unroll
    for (int d = 0; d <= R; d++)
        w2[d] = f2pack(__float_as_uint(wg[d]), __float_as_uint(wg[d]));

    const int jc = (threadIdx.x & 127) * 2;
    const int tg = threadIdx.x >> 7;
    float mx = hconv2<R, (M == 0)>(Bs, w2, Os, g_maph[b], row0, jc, tg);

    // block max -> one atomic
#pragma unroll
    for (int o = 16; o; o >>= 1)
        mx = fmaxf(mx, __shfl_xor_sync(0xFFFFFFFFu, mx, o));
    if ((threadIdx.x & 31) == 0) red[threadIdx.x >> 5] = mx;
    __syncthreads();
    if (threadIdx.x < 8) {
        float v = red[threadIdx.x];
#pragma unroll
        for (int o = 4; o; o >>= 1)
            v = fmaxf(v, __shfl_xor_sync(0xFFu, v, o));
        if (threadIdx.x == 0)
            atomicMax((int*)&g_max[M * BB + b], __float_as_int(v));
    }

    // ---- per-(m,b) completion wait (epoch-based, graph-replay safe) ----
    if (threadIdx.x == 0) {
        __threadfence();                               // publish maph + max
        unsigned my = atomicAdd(&g_done[M * BB + b], 1u) + 1u;
        unsigned gen = (my - 1u) / 8u;
        groupWait(&g_done[M * BB + b], (gen + 1u) * 8u);
        if (M == 1)                                    // need target map + its max
            groupWait(&g_done[0 * BB + b], (gen + 1u) * 8u);
        __threadfence();                               // acquire
    }
    __syncthreads();

    // ---- finalize own tile from smem ----
    const size_t plane = (size_t)HH * WW;
    float* ob = out + (size_t)b * 5 * plane;
    float mo = g_max[M * BB + b]; float so = 1.0f / ((mo == 0.f) ? 1.f : mo);
    float st = 0.f;
    if (M == 1) { float mt = g_max[b]; st = 1.0f / ((mt == 0.f) ? 1.f : mt); }

    for (int idx = threadIdx.x; idx < TH * (WW / 2); idx += NT) {
        const int row = idx >> 7, c2 = idx & 127;
        float2 v = __half22float2(*(__half2*)&Os[idx]);
        v.x *= so; v.y *= so;
        const size_t px = (size_t)(row0 + row) * WW + 2 * c2;
        *(float2*)(ob + (size_t)(M + 1) * plane + px) = v;
        if (M == 1) {
            uint32_t twd = g_maph[b][(size_t)(row0 + row) * (WW / 2) + c2];
            float2 t = __half22float2(*(__half2*)&twd);
            float2 mu = make_float2(t.x * st * v.x, t.y * st * v.y);
            *(float2*)(ob + 4 * plane + px) = mu;
        }
    }
}

// ============ Kernel 2: maps + in-kernel finalize ============
__global__ void __launch_bounds__(NT, 3) mapFinK(float* __restrict__ out) {
    extern __shared__ char smem[];
    float* LUT = (float*)smem;
    float* Bs = (float*)(smem + OFF_BS);
    uint32_t* Os = (uint32_t*)(smem + OFF_OS);
    __shared__ float red[8];

    const int row0 = blockIdx.x * TH;
    const int b = blockIdx.y;
    const int m = blockIdx.z;

    if (m == 2)
        runMapFin<2, 2>(b, 2.0f, row0, LUT, Bs, Os, red, out);   // hist, sigma=0.5
    else if (m == 1)
        runMapFin<5, 1>(b, 0.5f, row0, LUT, Bs, Os, red, out);   // cost, sigma=1
    else
        runMapFin<5, 0>(b, 0.5f, row0, LUT, Bs, Os, red, out);   // target, sigma=1
}

extern "C" void kernel_launch(void* const* d_in, const int* in_sizes, int n_in,
                              void* d_out, int out_size) {
    const float* x = (const float*)d_in[0];
    float* out = (float*)d_out;

    cudaFuncSetAttribute(mapFinK, cudaFuncAttributeMaxDynamicSharedMemorySize, SMEM_BYTES);

    bitK<<<dim3(8, BB, 4), NT>>>(x, out);
    mapFinK<<<dim3(HH / TH, BB, 3), NT, SMEM_BYTES>>>(out);
}

// round 11
// speedup vs baseline: 1.2363x; 1.2363x over previous
#include <cuda_runtime.h>
#include <cuda_fp16.h>
#include <cstdint>

#define BB 64
#define HH 256
#define WW 256
#define TH 64                      // output rows per mapK tile
#define NT 256
#define ARMAX (TH + 10)            // 74 bits-rows incl R=5 halo
#define SBW 10                     // padded bits row: zero word each side of 8

typedef unsigned long long ull;

__device__ __align__(16) uint32_t g_bits[3][BB][HH][8];        // 1 bit/px masks
__device__ __align__(16) uint32_t g_maph[3][BB][HH * WW / 2];  // fp16x2 unnormalized maps
__device__ float g_max[3 * BB];    // zero-init; atomicMax idempotent across replays

__device__ __forceinline__ int map_ch(int m) { return (m == 0) ? 2 : (m == 1) ? 1 : 3; }

// ---- packed f32x2 helpers (sm_103a) ----
__device__ __forceinline__ ull f2pack(uint32_t lo, uint32_t hi) {
    ull r; asm("mov.b64 %0, {%1, %2};" : "=l"(r) : "r"(lo), "r"(hi)); return r;
}
__device__ __forceinline__ void f2unpack(ull v, float& lo, float& hi) {
    asm("mov.b64 {%0, %1}, %2;" : "=f"(lo), "=f"(hi) : "l"(v));
}
__device__ __forceinline__ ull f2add(ull a, ull b) {
    ull r; asm("add.rn.f32x2 %0, %1, %2;" : "=l"(r) : "l"(a), "l"(b)); return r;
}
__device__ __forceinline__ ull f2mul(ull a, ull b) {
    ull r; asm("mul.rn.f32x2 %0, %1, %2;" : "=l"(r) : "l"(a), "l"(b)); return r;
}
__device__ __forceinline__ ull f2fma(ull a, ull b, ull c) {
    ull r; asm("fma.rn.f32x2 %0, %1, %2, %3;" : "=l"(r) : "l"(a), "l"(b), "l"(c)); return r;
}

// ============ Kernel 1: threshold channels into bit array + ch0 copy ============
__global__ void __launch_bounds__(NT) bitK(const float* __restrict__ x,
                                           float* __restrict__ out) {
    const int b = blockIdx.y;
    const int z = blockIdx.z;
    const size_t plane = (size_t)HH * WW;

    if (z == 3) {                       // ch0 passthrough: 8192 floats per block
        const size_t off = (size_t)blockIdx.x * 8192;
        const float4* s = (const float4*)(x + (size_t)b * 4 * plane + off);
        float4* d = (float4*)(out + (size_t)b * 5 * plane + off);
#pragma unroll
        for (int k = 0; k < 8; k++)
            d[threadIdx.x + 256 * k] = s[threadIdx.x + 256 * k];
        return;
    }

    const int m = z;
    const float* src = x + ((size_t)b * 4 + map_ch(m)) * plane;
    const int warp = threadIdx.x >> 5;
    const int lane = threadIdx.x & 31;
    const int r0 = blockIdx.x * 32 + warp * 4;

#pragma unroll
    for (int rr = 0; rr < 4; rr++) {
        const int r = r0 + rr;
        const float* rp = src + (size_t)r * WW;
        float v[8];
#pragma unroll
        for (int k = 0; k < 8; k++) v[k] = rp[32 * k + lane];
        uint32_t mine = 0;
#pragma unroll
        for (int k = 0; k < 8; k++) {
            uint32_t w = __ballot_sync(0xFFFFFFFFu, v[k] > 0.f);
            if (lane == k) mine = w;
        }
        if (lane < 8) g_bits[m][b][r][lane] = mine;
    }
}

// ============ LUT build: LUT[i] = sum over set bits p of wg[|p - R|] ============
template <int R>
__device__ __forceinline__ void buildLUT(const float* wg, float* LUT) {
    if constexpr (R == 5) {
        const int t = threadIdx.x;           // entry i = t*8 + j; bits 3..10 from t
        float base = 0.f;
#pragma unroll
        for (int b = 0; b < 8; b++) {
            int pos = b + 3;
            int ai = (pos < 5) ? (5 - pos) : (pos - 5);
            if ((t >> b) & 1) base += wg[ai];
        }
        float comb[8];
        comb[0] = 0.f;           comb[1] = wg[5];
        comb[2] = wg[4];         comb[3] = wg[5] + wg[4];
        comb[4] = wg[3];         comb[5] = wg[3] + wg[5];
        comb[6] = wg[3] + wg[4]; comb[7] = wg[3] + wg[4] + wg[5];
#pragma unroll
        for (int j = 0; j < 8; j++) LUT[t * 8 + j] = base + comb[j];
    } else {
        if (threadIdx.x < 32) {
            const int i = threadIdx.x;
            float s = 0.f;
#pragma unroll
            for (int b = 0; b < 5; b++) {
                int ai = (b < 2) ? (2 - b) : (b - 2);
                if ((i >> b) & 1) s += wg[ai];
            }
            LUT[i] = s;
        }
    }
}

// ============ Kernel 2: fused single-pass conv from bits ============
// One block = (64-row tile, b, m). Thread owns col pair (jc,jc+1) x 32 rows.
// Per row: 2 LDS.32 of mask words + funnel + 2 LUT lookups -> f2 W-value,
// pushed into a rolling (2R+1)-register H-conv window. No float smem intermediate.
template <int R, int M>
__device__ __forceinline__ void runMap(int b, float i2s, int row0,
                                       float* LUT, uint32_t (*Sb)[SBW], float* red) {
    constexpr int W = 2 * R + 1;
    constexpr int AR = TH + 2 * R;

    float wg[R + 1];
#pragma unroll
    for (int d = 0; d <= R; d++) wg[d] = __expf(-(float)(d * d) * i2s);

    buildLUT<R>(wg, LUT);

    // Fill bits tile Sb[AR][10] (word 0 and 9 zero). Coalesced: g_bits rows contiguous.
    for (int idx = threadIdx.x; idx < AR * 8; idx += NT) {
        const int r = idx >> 3, w = idx & 7;
        const int gr = row0 - R + r;
        Sb[r][w + 1] = ((unsigned)gr < HH) ? g_bits[M][b][gr][w] : 0u;
    }
    for (int idx = threadIdx.x; idx < AR * 2; idx += NT)
        Sb[idx >> 1][(idx & 1) ? 9 : 0] = 0u;
    __syncthreads();

    ull w2[R + 1];
#pragma unroll
    for (int d = 0; d <= R; d++)
        w2[d] = f2pack(__float_as_uint(wg[d]), __float_as_uint(wg[d]));

    const int jc = (threadIdx.x & 127) * 2;   // column pair
    const int tg = threadIdx.x >> 7;          // row group (32 rows)
    const int t0 = tg * 32;

    // constant per-thread bit position of col jc-R within padded row
    const int bitpos = jc + 32 - R;
    const int wi = bitpos >> 5;
    const unsigned sh = bitpos & 31u;
    const uint32_t msk = (1u << W) - 1u;

    // rolling window of W-conv f2 values
    ull win[W];
#pragma unroll
    for (int k = 0; k < W; k++) {
        const uint32_t* rw = Sb[t0 + k];
        uint32_t plo = rw[wi], phi = rw[wi + 1];      // two scalar LDS (4B aligned)
        uint32_t v = __funnelshift_r(plo, phi, sh);
        win[k] = f2pack(__float_as_uint(LUT[v & msk]),
                        __float_as_uint(LUT[(v >> 1) & msk]));
    }

    uint32_t* gdst = g_maph[M][b];
    float mx = 0.f;
#pragma unroll
    for (int t = 0; t < 32; t++) {
        ull acc = f2mul(w2[0], win[R]);
#pragma unroll
        for (int d = 1; d <= R; d++)
            acc = f2fma(w2[d], f2add(win[R - d], win[R + d]), acc);
        float lo, hi; f2unpack(acc, lo, hi);
        uint32_t h2;
        asm("cvt.rn.f16x2.f32 %0, %1, %2;" : "=r"(h2) : "f"(hi), "f"(lo));
        gdst[(size_t)(row0 + t0 + t) * (WW / 2) + (jc >> 1)] = h2;
        mx = fmaxf(mx, fmaxf(lo, hi));
#pragma unroll
        for (int k = 0; k < W - 1; k++) win[k] = win[k + 1];
        if (t < 31) {
            const uint32_t* rw = Sb[t0 + t + W];
            uint32_t plo = rw[wi], phi = rw[wi + 1];
            uint32_t v = __funnelshift_r(plo, phi, sh);
            win[W - 1] = f2pack(__float_as_uint(LUT[v & msk]),
                                __float_as_uint(LUT[(v >> 1) & msk]));
        }
    }

    // block max -> one atomic (values >= 0; int compare order-preserving)
#pragma unroll
    for (int o = 16; o; o >>= 1)
        mx = fmaxf(mx, __shfl_xor_sync(0xFFFFFFFFu, mx, o));
    if ((threadIdx.x & 31) == 0) red[threadIdx.x >> 5] = mx;
    __syncthreads();
    if (threadIdx.x < 8) {
        float v = red[threadIdx.x];
#pragma unroll
        for (int o = 4; o; o >>= 1)
            v = fmaxf(v, __shfl_xor_sync(0xFFu, v, o));
        if (threadIdx.x == 0)
            atomicMax((int*)&g_max[M * BB + b], __float_as_int(v));
    }
}

__global__ void __launch_bounds__(NT) mapK() {
    __shared__ float LUT[2048];
    __shared__ uint32_t Sb[ARMAX][SBW];
    __shared__ float red[8];

    const int row0 = blockIdx.x * TH;
    const int b = blockIdx.y;
    const int m = blockIdx.z;

    if (m == 2)
        runMap<2, 2>(b, 2.0f, row0, LUT, Sb, red);   // hist,   sigma=0.5
    else if (m == 1)
        runMap<5, 1>(b, 0.5f, row0, LUT, Sb, red);   // cost,   sigma=1
    else
        runMap<5, 0>(b, 0.5f, row0, LUT, Sb, red);   // target, sigma=1
}

// ============ Kernel 3: normalize + write ch1..ch4 (R8-identical) ============
__global__ void __launch_bounds__(256) finK(float* __restrict__ out) {
    const int b = blockIdx.y;
    const size_t px = ((size_t)blockIdx.x << 10) | ((size_t)threadIdx.x << 2);
    const size_t plane = (size_t)HH * WW;

    float mt = g_max[b];          float st = 1.0f / ((mt == 0.f) ? 1.f : mt);
    float mc = g_max[BB + b];     float sc = 1.0f / ((mc == 0.f) ? 1.f : mc);
    float mh = g_max[2 * BB + b]; float sh = 1.0f / ((mh == 0.f) ? 1.f : mh);

    uint2 tw = *(const uint2*)(&g_maph[0][b][px >> 1]);
    uint2 cw = *(const uint2*)(&g_maph[1][b][px >> 1]);
    uint2 hw = *(const uint2*)(&g_maph[2][b][px >> 1]);

    float2 ta = __half22float2(*(__half2*)&tw.x), tb = __half22float2(*(__half2*)&tw.y);
    float2 ca = __half22float2(*(__half2*)&cw.x), cb = __half22float2(*(__half2*)&cw.y);
    float2 ha = __half22float2(*(__half2*)&hw.x), hb = __half22float2(*(__half2*)&hw.y);

    float4 t = make_float4(ta.x * st, ta.y * st, tb.x * st, tb.y * st);
    float4 c = make_float4(ca.x * sc, ca.y * sc, cb.x * sc, cb.y * sc);
    float4 h = make_float4(ha.x * sh, ha.y * sh, hb.x * sh, hb.y * sh);
    float4 mu = make_float4(t.x * c.x, t.y * c.y, t.z * c.z, t.w * c.w);

    float* ob = out + (size_t)b * 5 * plane;
    *(float4*)(ob + plane + px) = t;
    *(float4*)(ob + 2 * plane + px) = c;
    *(float4*)(ob + 3 * plane + px) = h;
    *(float4*)(ob + 4 * plane + px) = mu;
}

extern "C" void kernel_launch(void* const* d_in, const int* in_sizes, int n_in,
                              void* d_out, int out_size) {
    const float* x = (const float*)d_in[0];
    float* out = (float*)d_out;

    bitK<<<dim3(8, BB, 4), NT>>>(x, out);
    mapK<<<dim3(HH / TH, BB, 3), NT>>>();
    finK<<<dim3(64, BB), 256>>>(out);
}